// round 1
// baseline (speedup 1.0000x reference)
#include <cuda_runtime.h>
#include <cuda_bf16.h>
#include <cstdint>

#define BATCH 16
#define CIN   80
#define CMID  256
#define TLEN  4096
#define KW    5
#define EMB   128
#define KD    24
#define DSTR  12
#define TP    341
#define VQD   16
#define NQ    8
#define NCODE 256

#define EA_SIZE (BATCH*EMB*TP)     // 698368
#define POSN    (BATCH*TP)         // 5456

// -------- scratch (device globals; no runtime allocation) --------
__device__ float g_x1[(size_t)BATCH*CMID*TLEN];   // after conv1+bn+relu
__device__ float g_x2[(size_t)BATCH*CMID*TLEN];   // after conv2+bn+relu
__device__ float g_z [(size_t)POSN*VQD];          // projected latents [b*TP+tp][d]

// ============================================================================
// Kernel 1: conv1 (80->256, k=5, pad=2) + BN + ReLU
// grid (TLEN/128, 256/32, BATCH), block 256
// smem: xs[80][132] + ws[400][32]  (dynamic, 93440 B)
// ============================================================================
#define K1_SMEM ((80*132 + 400*32)*4)

__global__ __launch_bounds__(256, 2)
void conv1_kernel(const float* __restrict__ mel,
                  const float* __restrict__ w1, const float* __restrict__ b1,
                  const float* __restrict__ g1, const float* __restrict__ be1,
                  const float* __restrict__ m1, const float* __restrict__ v1)
{
    extern __shared__ float sm1[];
    float* xs = sm1;             // [80][132]
    float* ws = sm1 + 80*132;    // [400][32]  indexed [ci*5+k][co]

    const int t0  = blockIdx.x * 128;
    const int co0 = blockIdx.y * 32;
    const int b   = blockIdx.z;
    const int tid = threadIdx.x;
    const int co_l = tid & 31;
    const int tg   = tid >> 5;   // 0..7, 16 t each

    const float* melb = mel + (size_t)b*CIN*TLEN;
    for (int i = tid; i < 80*132; i += 256) {
        int ci = i / 132, j = i % 132;
        int t = t0 - 2 + j;
        xs[i] = (t >= 0 && t < TLEN) ? melb[(size_t)ci*TLEN + t] : 0.f;
    }
    for (int i = tid; i < 400*32; i += 256) {
        int co = i & 31, r = i >> 5;          // r = ci*5+k
        ws[i] = w1[(size_t)(co0+co)*400 + r];
    }
    __syncthreads();

    float acc[16];
#pragma unroll
    for (int i = 0; i < 16; i++) acc[i] = 0.f;

#pragma unroll 2
    for (int ci = 0; ci < 80; ci++) {
        float xv[20];
        const float4* xp = (const float4*)(xs + ci*132 + tg*16);
#pragma unroll
        for (int q = 0; q < 5; q++) {
            float4 v = xp[q];
            xv[4*q] = v.x; xv[4*q+1] = v.y; xv[4*q+2] = v.z; xv[4*q+3] = v.w;
        }
#pragma unroll
        for (int k = 0; k < 5; k++) {
            float w = ws[(ci*5+k)*32 + co_l];
#pragma unroll
            for (int i = 0; i < 16; i++) acc[i] = fmaf(w, xv[i+k], acc[i]);
        }
    }

    const int co = co0 + co_l;
    float scale = g1[co] * rsqrtf(v1[co] + 1e-5f);
    float bias  = (b1[co] - m1[co]) * scale + be1[co];
    float* outp = g_x1 + (size_t)b*CMID*TLEN + (size_t)co*TLEN + t0 + tg*16;
#pragma unroll
    for (int i = 0; i < 16; i++) {
        float y = fmaf(acc[i], scale, bias);
        outp[i] = y > 0.f ? y : 0.f;
    }
}

// ============================================================================
// Kernel 2: conv2 (256->256, k=5, pad=2) + BN + ReLU
// grid (TLEN/128, 256/32, BATCH), block 256; ci chunked by 32. static smem.
// ============================================================================
__global__ __launch_bounds__(256, 2)
void conv2_kernel(const float* __restrict__ w2, const float* __restrict__ b2,
                  const float* __restrict__ g2, const float* __restrict__ be2,
                  const float* __restrict__ m2, const float* __restrict__ v2)
{
    __shared__ float xs[32*132];
    __shared__ float ws[160*32];   // [ci*5+k][co], ci within chunk

    const int t0  = blockIdx.x * 128;
    const int co0 = blockIdx.y * 32;
    const int b   = blockIdx.z;
    const int tid = threadIdx.x;
    const int co_l = tid & 31;
    const int tg   = tid >> 5;

    const float* x1b = g_x1 + (size_t)b*CMID*TLEN;

    float acc[16];
#pragma unroll
    for (int i = 0; i < 16; i++) acc[i] = 0.f;

    for (int c0 = 0; c0 < CMID; c0 += 32) {
        __syncthreads();
        for (int i = tid; i < 32*132; i += 256) {
            int ci = i / 132, j = i % 132;
            int t = t0 - 2 + j;
            xs[i] = (t >= 0 && t < TLEN) ? x1b[(size_t)(c0+ci)*TLEN + t] : 0.f;
        }
        for (int i = tid; i < 160*32; i += 256) {
            int co = i & 31, r = i >> 5;      // r = ci*5+k (ci local)
            ws[i] = w2[(size_t)(co0+co)*1280 + (size_t)c0*5 + r];
        }
        __syncthreads();

#pragma unroll 2
        for (int ci = 0; ci < 32; ci++) {
            float xv[20];
            const float4* xp = (const float4*)(xs + ci*132 + tg*16);
#pragma unroll
            for (int q = 0; q < 5; q++) {
                float4 v = xp[q];
                xv[4*q] = v.x; xv[4*q+1] = v.y; xv[4*q+2] = v.z; xv[4*q+3] = v.w;
            }
#pragma unroll
            for (int k = 0; k < 5; k++) {
                float w = ws[(ci*5+k)*32 + co_l];
#pragma unroll
                for (int i = 0; i < 16; i++) acc[i] = fmaf(w, xv[i+k], acc[i]);
            }
        }
    }

    const int co = co0 + co_l;
    float scale = g2[co] * rsqrtf(v2[co] + 1e-5f);
    float bias  = (b2[co] - m2[co]) * scale + be2[co];
    float* outp = g_x2 + (size_t)b*CMID*TLEN + (size_t)co*TLEN + t0 + tg*16;
#pragma unroll
    for (int i = 0; i < 16; i++) {
        float y = fmaf(acc[i], scale, bias);
        outp[i] = y > 0.f ? y : 0.f;
    }
}

// ============================================================================
// Kernel 3: downsample conv (256->128, k=24, stride=12, pad=6) -> d_out e_a
// grid (ceil(341/12)=29, 2, BATCH), block 128
// smem: xs[16][156] + ws[384][64]  (dynamic, 108288 B)
// ============================================================================
#define K3_SMEM ((16*156 + 384*64)*4)

__global__ __launch_bounds__(128, 2)
void down_kernel(const float* __restrict__ wd, const float* __restrict__ bd,
                 float* __restrict__ out)
{
    extern __shared__ float sm3[];
    float* xs = sm3;             // [16][156]
    float* ws = sm3 + 16*156;    // [ci*24+k][64]

    const int tp0 = blockIdx.x * 12;
    const int co0 = blockIdx.y * 64;
    const int b   = blockIdx.z;
    const int tid = threadIdx.x;
    const int co_l = tid & 63;
    const int tg   = tid >> 6;   // 0..1, 6 t' each

    const float* x2b = g_x2 + (size_t)b*CMID*TLEN;
    const int base = tp0*DSTR - 6;

    float acc[6];
#pragma unroll
    for (int i = 0; i < 6; i++) acc[i] = 0.f;

    for (int c0 = 0; c0 < CMID; c0 += 16) {
        __syncthreads();
        for (int i = tid; i < 16*156; i += 128) {
            int ci = i / 156, j = i % 156;
            int t = base + j;
            xs[i] = (t >= 0 && t < TLEN) ? x2b[(size_t)(c0+ci)*TLEN + t] : 0.f;
        }
        for (int i = tid; i < 384*64; i += 128) {
            int co = i & 63, r = i >> 6;      // r = ci*24+k (ci local)
            ws[i] = wd[(size_t)(co0+co)*6144 + (size_t)c0*24 + r];
        }
        __syncthreads();

#pragma unroll 1
        for (int ci = 0; ci < 16; ci++) {
            float xr[84];
            const float4* xp = (const float4*)(xs + ci*156 + tg*72);
#pragma unroll
            for (int q = 0; q < 21; q++) {
                float4 v = xp[q];
                xr[4*q] = v.x; xr[4*q+1] = v.y; xr[4*q+2] = v.z; xr[4*q+3] = v.w;
            }
#pragma unroll
            for (int k = 0; k < 24; k++) {
                float w = ws[(ci*24+k)*64 + co_l];
#pragma unroll
                for (int tt = 0; tt < 6; tt++)
                    acc[tt] = fmaf(w, xr[tt*12 + k], acc[tt]);
            }
        }
    }

    const int co = co0 + co_l;
    const float bv = bd[co];
#pragma unroll
    for (int tt = 0; tt < 6; tt++) {
        int tp = tp0 + tg*6 + tt;
        if (tp < TP)
            out[(size_t)b*EMB*TP + (size_t)co*TP + tp] = acc[tt] + bv;
    }
}

// ============================================================================
// Kernel 4: 1x1 projection e_a(128) -> z(16), reads e_a from d_out
// ============================================================================
__global__ __launch_bounds__(256)
void proj_kernel(const float* __restrict__ out,
                 const float* __restrict__ wp, const float* __restrict__ bp)
{
    int idx = blockIdx.x * 256 + threadIdx.x;
    if (idx >= POSN * VQD) return;
    int d  = idx & 15;
    int bt = idx >> 4;                  // b*TP + tp
    int b  = bt / TP, tp = bt % TP;
    const float* ea = out + (size_t)b*EMB*TP + tp;   // stride TP over channels
    float s = bp[d];
#pragma unroll 4
    for (int e = 0; e < EMB; e++)
        s = fmaf(wp[d*EMB + e], ea[(size_t)e*TP], s);
    g_z[(size_t)bt*VQD + d] = s;
}

// ============================================================================
// Kernel 5: residual VQ, 8 stages; one thread per (b,t') position.
// Writes indices (as float) to d_out after the e_a block.
// ============================================================================
__global__ __launch_bounds__(256)
void rvq_kernel(const float* __restrict__ codebooks, float* __restrict__ out)
{
    __shared__ float cbs[NCODE * VQD];   // 16 KB
    __shared__ float cc[NCODE];

    const int tid = threadIdx.x;
    const int pos = blockIdx.x * 256 + tid;       // b*TP + tp
    const bool valid = pos < POSN;

    float r[VQD];
    if (valid) {
#pragma unroll
        for (int d = 0; d < VQD; d++) r[d] = g_z[(size_t)pos*VQD + d];
    }

    for (int q = 0; q < NQ; q++) {
        __syncthreads();
        for (int i = tid; i < NCODE*VQD; i += 256)
            cbs[i] = codebooks[(size_t)q*NCODE*VQD + i];
        __syncthreads();
        {
            float s = 0.f;
#pragma unroll
            for (int d = 0; d < VQD; d++) {
                float c = cbs[tid*VQD + d];
                s = fmaf(c, c, s);
            }
            cc[tid] = s;
        }
        __syncthreads();

        if (valid) {
            int best = 0;
            float bestd = 3.4e38f;
            for (int code = 0; code < NCODE; code++) {
                float dot = 0.f;
#pragma unroll
                for (int d = 0; d < VQD; d++)
                    dot = fmaf(r[d], cbs[code*VQD + d], dot);
                float sc = cc[code] - 2.f*dot;    // argmin-equivalent to full dist
                if (sc < bestd) { bestd = sc; best = code; }
            }
            out[EA_SIZE + (size_t)q*POSN + pos] = (float)best;
#pragma unroll
            for (int d = 0; d < VQD; d++) r[d] -= cbs[best*VQD + d];
        }
    }
}

// ============================================================================
extern "C" void kernel_launch(void* const* d_in, const int* in_sizes, int n_in,
                              void* d_out, int out_size)
{
    const float* mel = (const float*)d_in[0];
    const float* w1  = (const float*)d_in[1];
    const float* b1  = (const float*)d_in[2];
    const float* g1  = (const float*)d_in[3];
    const float* be1 = (const float*)d_in[4];
    const float* m1  = (const float*)d_in[5];
    const float* v1  = (const float*)d_in[6];
    const float* w2  = (const float*)d_in[7];
    const float* b2  = (const float*)d_in[8];
    const float* g2  = (const float*)d_in[9];
    const float* be2 = (const float*)d_in[10];
    const float* m2  = (const float*)d_in[11];
    const float* v2  = (const float*)d_in[12];
    const float* wd  = (const float*)d_in[13];
    const float* bd  = (const float*)d_in[14];
    const float* wp  = (const float*)d_in[15];
    const float* bp  = (const float*)d_in[16];
    const float* cb  = (const float*)d_in[17];
    float* out = (float*)d_out;

    cudaFuncSetAttribute(conv1_kernel, cudaFuncAttributeMaxDynamicSharedMemorySize, K1_SMEM);
    cudaFuncSetAttribute(down_kernel,  cudaFuncAttributeMaxDynamicSharedMemorySize, K3_SMEM);

    conv1_kernel<<<dim3(TLEN/128, CMID/32, BATCH), 256, K1_SMEM>>>(mel, w1, b1, g1, be1, m1, v1);
    conv2_kernel<<<dim3(TLEN/128, CMID/32, BATCH), 256>>>(w2, b2, g2, be2, m2, v2);
    down_kernel<<<dim3((TP + 11)/12, EMB/64, BATCH), 128, K3_SMEM>>>(wd, bd, out);
    proj_kernel<<<(POSN*VQD + 255)/256, 256>>>(out, wp, bp);
    rvq_kernel<<<(POSN + 255)/256, 256>>>(cb, out);
}

// round 4
// speedup vs baseline: 1.2402x; 1.2402x over previous
#include <cuda_runtime.h>
#include <cuda_bf16.h>
#include <cstdint>

#define BATCH 16
#define CIN   80
#define CMID  256
#define TLEN  4096
#define EMB   128
#define DSTR  12
#define TP    341
#define VQD   16
#define NQ    8
#define NCODE 256

#define EA_SIZE (BATCH*EMB*TP)     // 698368
#define POSN    (BATCH*TP)         // 5456

typedef unsigned long long u64;

// packed fp32x2 FMA (Blackwell sm_100+): 2 IEEE fp32 FMAs per issue, fmaf rounding
__device__ __forceinline__ u64 ffma2(u64 a, u64 b, u64 c) {
    u64 d;
    asm("fma.rn.f32x2 %0, %1, %2, %3;" : "=l"(d) : "l"(a), "l"(b), "l"(c));
    return d;
}
__device__ __forceinline__ float2 u2f2(u64 u) {
    float2 f;
    asm("mov.b64 {%0, %1}, %2;" : "=f"(f.x), "=f"(f.y) : "l"(u));
    return f;
}

// -------- scratch (device globals; no runtime allocation) --------
__device__ float g_x1[(size_t)BATCH*CMID*TLEN];   // after conv1+bn+relu
__device__ float g_x2[(size_t)BATCH*CMID*TLEN];   // after conv2+bn+relu
__device__ float g_z [(size_t)POSN*VQD];          // projected latents

// ============================================================================
// Kernel 1: conv1 (80->256, k=5, pad=2) + BN + ReLU.  f32x2-packed over co.
// grid (32, 4, 16), block 256. Each thread: 16 t x 2 co.
// ============================================================================
#define CCHUNK 16

__global__ __launch_bounds__(256, 2)
void conv1_kernel(const float* __restrict__ mel,
                  const float* __restrict__ w1, const float* __restrict__ b1,
                  const float* __restrict__ g1, const float* __restrict__ be1,
                  const float* __restrict__ m1, const float* __restrict__ v1)
{
    __shared__ float2 xsd[CCHUNK*132];
    __shared__ float  ws[CCHUNK*5*64];

    const int t0  = blockIdx.x * 128;
    const int co0 = blockIdx.y * 64;
    const int b   = blockIdx.z;
    const int tid = threadIdx.x;
    const int cp  = tid & 31;      // co-pair index
    const int tg  = tid >> 5;      // 0..7, 16 t each

    const float* xb = mel + (size_t)b*CIN*TLEN;

    u64 acc[16];
#pragma unroll
    for (int i = 0; i < 16; i++) acc[i] = 0ull;

    for (int c0 = 0; c0 < CIN; c0 += CCHUNK) {
        __syncthreads();
        for (int i = tid; i < CCHUNK*132; i += 256) {
            int ci = i / 132, j = i % 132;
            int t = t0 - 2 + j;
            float v = (t >= 0 && t < TLEN) ? xb[(size_t)(c0+ci)*TLEN + t] : 0.f;
            xsd[i] = make_float2(v, v);
        }
        for (int i = tid; i < CCHUNK*5*64; i += 256) {
            int co = i & 63, r = i >> 6;           // r = ci_local*5+k
            ws[i] = w1[(size_t)(co0+co)*(CIN*5) + c0*5 + r];
        }
        __syncthreads();

#pragma unroll 1
        for (int ci = 0; ci < CCHUNK; ci++) {
            u64 xv[20];
            const ulonglong2* xp = (const ulonglong2*)(xsd + ci*132 + tg*16);
#pragma unroll
            for (int q = 0; q < 10; q++) { ulonglong2 v = xp[q]; xv[2*q] = v.x; xv[2*q+1] = v.y; }
#pragma unroll
            for (int k = 0; k < 5; k++) {
                u64 w = *(const u64*)(ws + (ci*5+k)*64 + 2*cp);
#pragma unroll
                for (int i = 0; i < 16; i++) acc[i] = ffma2(w, xv[i+k], acc[i]);
            }
        }
    }

    const int co = co0 + 2*cp;
    float s0 = g1[co]   * rsqrtf(v1[co]   + 1e-5f);
    float s1 = g1[co+1] * rsqrtf(v1[co+1] + 1e-5f);
    float bb0 = (b1[co]   - m1[co])   * s0 + be1[co];
    float bb1 = (b1[co+1] - m1[co+1]) * s1 + be1[co+1];
    float* o0 = g_x1 + (size_t)b*CMID*TLEN + (size_t)co*TLEN + t0 + tg*16;
    float* o1 = o0 + TLEN;
#pragma unroll
    for (int i = 0; i < 16; i++) {
        float2 v = u2f2(acc[i]);
        float y0 = fmaf(v.x, s0, bb0), y1 = fmaf(v.y, s1, bb1);
        o0[i] = y0 > 0.f ? y0 : 0.f;
        o1[i] = y1 > 0.f ? y1 : 0.f;
    }
}

// ============================================================================
// Kernel 2: conv2 (256->256, k=5, pad=2) + BN + ReLU. Same structure.
// ============================================================================
__global__ __launch_bounds__(256, 2)
void conv2_kernel(const float* __restrict__ w2, const float* __restrict__ b2,
                  const float* __restrict__ g2, const float* __restrict__ be2,
                  const float* __restrict__ m2, const float* __restrict__ v2)
{
    __shared__ float2 xsd[CCHUNK*132];
    __shared__ float  ws[CCHUNK*5*64];

    const int t0  = blockIdx.x * 128;
    const int co0 = blockIdx.y * 64;
    const int b   = blockIdx.z;
    const int tid = threadIdx.x;
    const int cp  = tid & 31;
    const int tg  = tid >> 5;

    const float* xb = g_x1 + (size_t)b*CMID*TLEN;

    u64 acc[16];
#pragma unroll
    for (int i = 0; i < 16; i++) acc[i] = 0ull;

    for (int c0 = 0; c0 < CMID; c0 += CCHUNK) {
        __syncthreads();
        for (int i = tid; i < CCHUNK*132; i += 256) {
            int ci = i / 132, j = i % 132;
            int t = t0 - 2 + j;
            float v = (t >= 0 && t < TLEN) ? xb[(size_t)(c0+ci)*TLEN + t] : 0.f;
            xsd[i] = make_float2(v, v);
        }
        for (int i = tid; i < CCHUNK*5*64; i += 256) {
            int co = i & 63, r = i >> 6;
            ws[i] = w2[(size_t)(co0+co)*(CMID*5) + c0*5 + r];
        }
        __syncthreads();

#pragma unroll 1
        for (int ci = 0; ci < CCHUNK; ci++) {
            u64 xv[20];
            const ulonglong2* xp = (const ulonglong2*)(xsd + ci*132 + tg*16);
#pragma unroll
            for (int q = 0; q < 10; q++) { ulonglong2 v = xp[q]; xv[2*q] = v.x; xv[2*q+1] = v.y; }
#pragma unroll
            for (int k = 0; k < 5; k++) {
                u64 w = *(const u64*)(ws + (ci*5+k)*64 + 2*cp);
#pragma unroll
                for (int i = 0; i < 16; i++) acc[i] = ffma2(w, xv[i+k], acc[i]);
            }
        }
    }

    const int co = co0 + 2*cp;
    float s0 = g2[co]   * rsqrtf(v2[co]   + 1e-5f);
    float s1 = g2[co+1] * rsqrtf(v2[co+1] + 1e-5f);
    float bb0 = (b2[co]   - m2[co])   * s0 + be2[co];
    float bb1 = (b2[co+1] - m2[co+1]) * s1 + be2[co+1];
    float* o0 = g_x2 + (size_t)b*CMID*TLEN + (size_t)co*TLEN + t0 + tg*16;
    float* o1 = o0 + TLEN;
#pragma unroll
    for (int i = 0; i < 16; i++) {
        float2 v = u2f2(acc[i]);
        float y0 = fmaf(v.x, s0, bb0), y1 = fmaf(v.y, s1, bb1);
        o0[i] = y0 > 0.f ? y0 : 0.f;
        o1[i] = y1 > 0.f ? y1 : 0.f;
    }
}

// ============================================================================
// Kernel 3: downsample conv (256->128, k=24, stride=12, pad=6) -> d_out e_a.
// grid (15, 2, 16), block 256. Thread: 3 t' x 2 co. ci chunked by 8.
// No register staging of x (each x value is used exactly once per thread),
// direct LDS.64 broadcast reads instead -> ~30 regs, no spill.
// dynamic smem: xsd[8][300] float2 + ws[192][64] float = 68352 B
// ============================================================================
#define DC 8
#define D_SMEM (DC*300*8 + DC*24*64*4)

__global__ __launch_bounds__(256, 3)
void down_kernel(const float* __restrict__ wd, const float* __restrict__ bd,
                 float* __restrict__ out)
{
    extern __shared__ float smd[];
    float2* xsd = (float2*)smd;            // [8][300] dup pairs
    float*  ws  = smd + DC*300*2;          // [192][64]

    const int tp0 = blockIdx.x * 24;
    const int co0 = blockIdx.y * 64;
    const int b   = blockIdx.z;
    const int tid = threadIdx.x;
    const int cp  = tid & 31;
    const int tg  = tid >> 5;              // 0..7, 3 t' each

    const float* xb = g_x2 + (size_t)b*CMID*TLEN;
    const int base = tp0*DSTR - 6;

    u64 acc[3] = {0ull, 0ull, 0ull};

    for (int c0 = 0; c0 < CMID; c0 += DC) {
        __syncthreads();
        for (int i = tid; i < DC*300; i += 256) {
            int ci = i / 300, j = i % 300;
            int t = base + j;
            float v = (t >= 0 && t < TLEN) ? xb[(size_t)(c0+ci)*TLEN + t] : 0.f;
            xsd[i] = make_float2(v, v);
        }
        for (int i = tid; i < DC*24*64; i += 256) {
            int co = i & 63, r = i >> 6;          // r = ci_local*24+k
            ws[i] = wd[(size_t)(co0+co)*(CMID*24) + c0*24 + r];
        }
        __syncthreads();

#pragma unroll 1
        for (int ci = 0; ci < DC; ci++) {
            const u64* xrow = (const u64*)(xsd + ci*300 + tg*36);
            const float* wrow = ws + ci*24*64 + 2*cp;
#pragma unroll 4
            for (int k = 0; k < 24; k++) {
                u64 w = *(const u64*)(wrow + k*64);
#pragma unroll
                for (int tt = 0; tt < 3; tt++)
                    acc[tt] = ffma2(w, xrow[tt*12 + k], acc[tt]);
            }
        }
    }

    const int co = co0 + 2*cp;
    const float b0 = bd[co], b1v = bd[co+1];
#pragma unroll
    for (int tt = 0; tt < 3; tt++) {
        int tp = tp0 + tg*3 + tt;
        if (tp < TP) {
            float2 v = u2f2(acc[tt]);
            out[(size_t)b*EMB*TP + (size_t)co*TP + tp]     = v.x + b0;
            out[(size_t)b*EMB*TP + (size_t)(co+1)*TP + tp] = v.y + b1v;
        }
    }
}

// ============================================================================
// Kernel 4: 1x1 projection e_a(128) -> z(16).  Coalesced smem tile version.
// ============================================================================
__global__ __launch_bounds__(256)
void proj_kernel(const float* __restrict__ out,
                 const float* __restrict__ wp, const float* __restrict__ bp)
{
    __shared__ float xs[EMB*64];     // [e][tp_l]  32 KB
    __shared__ float wps[VQD*EMB];   // [d][e]      8 KB

    const int tp0 = blockIdx.x * 64;
    const int b   = blockIdx.y;
    const int tid = threadIdx.x;
    const int tp_l = tid & 63;
    const int dbase = tid >> 6;      // 0..3

    for (int i = tid; i < EMB*64; i += 256) {
        int e = i >> 6, tl = i & 63;
        int tp = tp0 + tl;
        xs[i] = (tp < TP) ? out[(size_t)b*EMB*TP + (size_t)e*TP + tp] : 0.f;
    }
    for (int i = tid; i < VQD*EMB; i += 256) wps[i] = wp[i];
    __syncthreads();

    float acc[4] = {0.f, 0.f, 0.f, 0.f};
    for (int e = 0; e < EMB; e++) {
        float xv = xs[e*64 + tp_l];
#pragma unroll
        for (int dd = 0; dd < 4; dd++)
            acc[dd] = fmaf(wps[(dd*4 + dbase)*EMB + e], xv, acc[dd]);
    }

    int tp = tp0 + tp_l;
    if (tp < TP) {
#pragma unroll
        for (int dd = 0; dd < 4; dd++) {
            int d = dd*4 + dbase;
            g_z[((size_t)b*TP + tp)*VQD + d] = acc[dd] + bp[d];
        }
    }
}

// ============================================================================
// Kernel 5: residual VQ, 8 stages; one thread per (b,t') position.
// ============================================================================
__global__ __launch_bounds__(256)
void rvq_kernel(const float* __restrict__ codebooks, float* __restrict__ out)
{
    __shared__ float cbs[NCODE * VQD];
    __shared__ float cc[NCODE];

    const int tid = threadIdx.x;
    const int pos = blockIdx.x * 256 + tid;
    const bool valid = pos < POSN;

    float r[VQD];
    if (valid) {
#pragma unroll
        for (int d = 0; d < VQD; d++) r[d] = g_z[(size_t)pos*VQD + d];
    }

    for (int q = 0; q < NQ; q++) {
        __syncthreads();
        for (int i = tid; i < NCODE*VQD; i += 256)
            cbs[i] = codebooks[(size_t)q*NCODE*VQD + i];
        __syncthreads();
        {
            float s = 0.f;
#pragma unroll
            for (int d = 0; d < VQD; d++) {
                float c = cbs[tid*VQD + d];
                s = fmaf(c, c, s);
            }
            cc[tid] = s;
        }
        __syncthreads();

        if (valid) {
            int best = 0;
            float bestd = 3.4e38f;
            for (int code = 0; code < NCODE; code++) {
                float dot = 0.f;
#pragma unroll
                for (int d = 0; d < VQD; d++)
                    dot = fmaf(r[d], cbs[code*VQD + d], dot);
                float sc = cc[code] - 2.f*dot;
                if (sc < bestd) { bestd = sc; best = code; }
            }
            out[EA_SIZE + (size_t)q*POSN + pos] = (float)best;
#pragma unroll
            for (int d = 0; d < VQD; d++) r[d] -= cbs[best*VQD + d];
        }
    }
}

// ============================================================================
extern "C" void kernel_launch(void* const* d_in, const int* in_sizes, int n_in,
                              void* d_out, int out_size)
{
    const float* mel = (const float*)d_in[0];
    const float* w1  = (const float*)d_in[1];
    const float* b1  = (const float*)d_in[2];
    const float* g1  = (const float*)d_in[3];
    const float* be1 = (const float*)d_in[4];
    const float* m1  = (const float*)d_in[5];
    const float* v1  = (const float*)d_in[6];
    const float* w2  = (const float*)d_in[7];
    const float* b2  = (const float*)d_in[8];
    const float* g2  = (const float*)d_in[9];
    const float* be2 = (const float*)d_in[10];
    const float* m2  = (const float*)d_in[11];
    const float* v2  = (const float*)d_in[12];
    const float* wd  = (const float*)d_in[13];
    const float* bd  = (const float*)d_in[14];
    const float* wp  = (const float*)d_in[15];
    const float* bp  = (const float*)d_in[16];
    const float* cb  = (const float*)d_in[17];
    float* out = (float*)d_out;

    cudaFuncSetAttribute(down_kernel, cudaFuncAttributeMaxDynamicSharedMemorySize, D_SMEM);

    conv1_kernel<<<dim3(TLEN/128, CMID/64, BATCH), 256>>>(mel, w1, b1, g1, be1, m1, v1);
    conv2_kernel<<<dim3(TLEN/128, CMID/64, BATCH), 256>>>(w2, b2, g2, be2, m2, v2);
    down_kernel<<<dim3((TP + 23)/24, EMB/64, BATCH), 256, D_SMEM>>>(wd, bd, out);
    proj_kernel<<<dim3((TP + 63)/64, BATCH), 256>>>(out, wp, bp);
    rvq_kernel<<<(POSN + 255)/256, 256>>>(cb, out);
}

// round 11
// speedup vs baseline: 1.4078x; 1.1352x over previous
#include <cuda_runtime.h>
#include <cuda_bf16.h>
#include <cstdint>

#define BATCH 16
#define CIN1  80
#define CMID  256
#define TLEN  4096
#define EMB   128
#define DSTR  12
#define TP    341
#define VQD   16
#define NQ    8
#define NCODE 256

#define EA_SIZE (BATCH*EMB*TP)     // 698368
#define POSN    (BATCH*TP)         // 5456

typedef unsigned long long u64;
typedef __nv_bfloat162 bf2;

// ---------------- helpers ----------------
__device__ __forceinline__ u64 ffma2(u64 a, u64 b, u64 c) {
    u64 d;
    asm("fma.rn.f32x2 %0, %1, %2, %3;" : "=l"(d) : "l"(a), "l"(b), "l"(c));
    return d;
}
__device__ __forceinline__ float2 u2f2(u64 u) {
    float2 f;
    asm("mov.b64 {%0, %1}, %2;" : "=f"(f.x), "=f"(f.y) : "l"(u));
    return f;
}
// 3-way bf16 split: x ~= h + m + l, residual ~2^-24 |x|
__device__ __forceinline__ void split3(float x, __nv_bfloat16& h, __nv_bfloat16& m,
                                       __nv_bfloat16& l) {
    h = __float2bfloat16_rn(x);
    float r1 = x - __bfloat162float(h);
    m = __float2bfloat16_rn(r1);
    float r2 = r1 - __bfloat162float(m);
    l = __float2bfloat16_rn(r2);
}
// D += A(16x16) * B(16x8), bf16 in, f32 accum
__device__ __forceinline__ void mma_bf16(float* c, unsigned a0, unsigned a1,
                                         unsigned a2, unsigned a3,
                                         unsigned b0, unsigned b1) {
    asm("mma.sync.aligned.m16n8k16.row.col.f32.bf16.bf16.f32 "
        "{%0,%1,%2,%3}, {%4,%5,%6,%7}, {%8,%9}, {%0,%1,%2,%3};"
        : "+f"(c[0]), "+f"(c[1]), "+f"(c[2]), "+f"(c[3])
        : "r"(a0), "r"(a1), "r"(a2), "r"(a3), "r"(b0), "r"(b1));
}

// -------- scratch (device globals; no runtime allocation) --------
__device__ float g_x1[(size_t)BATCH*CMID*TLEN];
__device__ float g_x2[(size_t)BATCH*CMID*TLEN];
__device__ float g_z [(size_t)POSN*VQD];
#define WT2_WORDS ((size_t)(CMID/16)*5*8*CMID)
#define WT1_WORDS ((size_t)(CIN1/16)*5*8*CMID)
__device__ bf2 g_wt2h[WT2_WORDS]; __device__ bf2 g_wt2m[WT2_WORDS]; __device__ bf2 g_wt2l[WT2_WORDS];
__device__ bf2 g_wt1h[WT1_WORDS]; __device__ bf2 g_wt1m[WT1_WORDS]; __device__ bf2 g_wt1l[WT1_WORDS];

__global__ void nop_kernel() {}

// ============================================================================
// Weight transform: w (256, Cin, 5) -> [chunk][kw][ci2][co] {ci even, ci odd}
// ============================================================================
__global__ void wtrans_kernel(const float* __restrict__ w,
                              bf2* __restrict__ th, bf2* __restrict__ tm,
                              bf2* __restrict__ tl, int Cin)
{
    int idx = blockIdx.x * 256 + threadIdx.x;
    int total = (Cin/16) * 5 * 8 * 256;
    if (idx >= total) return;
    int co   = idx & 255;
    int rest = idx >> 8;
    int ci2  = rest & 7;
    int kw   = (rest >> 3) % 5;
    int chunk = rest / 40;
    int ci0 = chunk*16 + 2*ci2;
    float w0 = w[(size_t)co*Cin*5 + (size_t)ci0*5 + kw];
    float w1 = w[(size_t)co*Cin*5 + (size_t)(ci0+1)*5 + kw];
    __nv_bfloat16 h0,m0,l0,h1,m1,l1;
    split3(w0, h0, m0, l0);
    split3(w1, h1, m1, l1);
    th[idx] = __halves2bfloat162(h0, h1);
    tm[idx] = __halves2bfloat162(m0, m1);
    tl[idx] = __halves2bfloat162(l0, l1);
}

// ============================================================================
// Implicit-GEMM conv (k=5, pad=2, Cout=256) + BN + ReLU, bf16x8 emulated fp32.
// Short-chain accumulation: 8 mmas into a zeroed temp C per (kw, frag), then
// RN fadd flush into main fp32 accumulators (defeats tensor-core RZ-chain bias).
// block 256 (8 warps), tile M=64 co x N=64 t; warp m16 x n32.
// ============================================================================
#define XSS 72
#define WSS 72

__global__ __launch_bounds__(256, 2)
void convmma_kernel(const float* __restrict__ X,
                    const bf2* __restrict__ wth, const bf2* __restrict__ wtm,
                    const bf2* __restrict__ wtl,
                    float* __restrict__ Y, int Cin,
                    const float* __restrict__ cb_, const float* __restrict__ g_,
                    const float* __restrict__ be_, const float* __restrict__ m_,
                    const float* __restrict__ v_)
{
    __shared__ bf2 xsh[8*XSS], xsm[8*XSS], xsl[8*XSS];
    __shared__ bf2 wsh[40*WSS], wsm[40*WSS], wsl[40*WSS];

    const int t0   = blockIdx.x * 64;
    const int co0  = blockIdx.y * 64;
    const int b    = blockIdx.z;
    const int tid  = threadIdx.x;
    const int lane = tid & 31;
    const int wid  = tid >> 5;
    const int wm   = wid & 3;
    const int wn   = wid >> 2;
    const int qr   = lane >> 2;
    const int qc   = lane & 3;

    const float* Xb = X + (size_t)b * Cin * TLEN;

    float cm[4][4];
#pragma unroll
    for (int j = 0; j < 4; j++)
#pragma unroll
        for (int i = 0; i < 4; i++) cm[j][i] = 0.f;

    const unsigned* uxsh = (const unsigned*)xsh;
    const unsigned* uxsm = (const unsigned*)xsm;
    const unsigned* uxsl = (const unsigned*)xsl;
    const unsigned* uwsh = (const unsigned*)wsh;
    const unsigned* uwsm = (const unsigned*)wsm;
    const unsigned* uwsl = (const unsigned*)wsl;

    const int nchunk = Cin >> 4;
    for (int chunk = 0; chunk < nchunk; chunk++) {
        __syncthreads();
        for (int i = tid; i < 8*68; i += 256) {
            int ci2 = i / 68, j = i % 68;
            int t = t0 - 2 + j;
            float x0 = 0.f, x1 = 0.f;
            if (t >= 0 && t < TLEN) {
                const float* xp = Xb + (size_t)(chunk*16 + 2*ci2)*TLEN + t;
                x0 = xp[0];
                x1 = xp[TLEN];
            }
            __nv_bfloat16 h0,m0,l0,h1,m1,l1;
            split3(x0, h0, m0, l0);
            split3(x1, h1, m1, l1);
            xsh[ci2*XSS + j] = __halves2bfloat162(h0, h1);
            xsm[ci2*XSS + j] = __halves2bfloat162(m0, m1);
            xsl[ci2*XSS + j] = __halves2bfloat162(l0, l1);
        }
        {
            const size_t srcbase = (size_t)chunk * 40 * 256;
            for (int i = tid; i < 40*64; i += 256) {
                int r = i >> 6, m = i & 63;
                size_t s = srcbase + (size_t)r*256 + co0 + m;
                wsh[r*WSS + m] = wth[s];
                wsm[r*WSS + m] = wtm[s];
                wsl[r*WSS + m] = wtl[s];
            }
        }
        __syncthreads();

#pragma unroll
        for (int kw = 0; kw < 5; kw++) {
            const int ra = (kw*8 + qc)*WSS + wm*16 + qr;
            const int rb = (kw*8 + qc + 4)*WSS + wm*16 + qr;
            unsigned Ah0 = uwsh[ra], Ah1 = uwsh[ra+8], Ah2 = uwsh[rb], Ah3 = uwsh[rb+8];
            unsigned Am0 = uwsm[ra], Am1 = uwsm[ra+8], Am2 = uwsm[rb], Am3 = uwsm[rb+8];
            unsigned Al0 = uwsl[ra], Al1 = uwsl[ra+8], Al2 = uwsl[rb], Al3 = uwsl[rb+8];
#pragma unroll
            for (int j = 0; j < 4; j++) {
                const int toff = wn*32 + j*8 + qr + kw;
                const int x0i = qc*XSS + toff;
                const int x1i = (qc+4)*XSS + toff;
                unsigned Bh0 = uxsh[x0i], Bh1 = uxsh[x1i];
                unsigned Bm0 = uxsm[x0i], Bm1 = uxsm[x1i];
                unsigned Bl0 = uxsl[x0i], Bl1 = uxsl[x1i];
                // short chain: 8 mmas into zeroed temp, then RN flush
                float ct[4] = {0.f, 0.f, 0.f, 0.f};
                mma_bf16(ct, Al0,Al1,Al2,Al3, Bm0,Bm1);   // l*m
                mma_bf16(ct, Am0,Am1,Am2,Am3, Bl0,Bl1);   // m*l
                mma_bf16(ct, Am0,Am1,Am2,Am3, Bm0,Bm1);   // m*m
                mma_bf16(ct, Al0,Al1,Al2,Al3, Bh0,Bh1);   // l*h
                mma_bf16(ct, Ah0,Ah1,Ah2,Ah3, Bl0,Bl1);   // h*l
                mma_bf16(ct, Am0,Am1,Am2,Am3, Bh0,Bh1);   // m*h
                mma_bf16(ct, Ah0,Ah1,Ah2,Ah3, Bm0,Bm1);   // h*m
                mma_bf16(ct, Ah0,Ah1,Ah2,Ah3, Bh0,Bh1);   // h*h
#pragma unroll
                for (int i = 0; i < 4; i++) cm[j][i] += ct[i];
            }
        }
    }

    const int r0 = co0 + wm*16 + qr;
    const int r1 = r0 + 8;
    float s0 = g_[r0] * rsqrtf(v_[r0] + 1e-5f);
    float s1 = g_[r1] * rsqrtf(v_[r1] + 1e-5f);
    float bb0 = (cb_[r0] - m_[r0]) * s0 + be_[r0];
    float bb1 = (cb_[r1] - m_[r1]) * s1 + be_[r1];
    float* Y0 = Y + (size_t)b*CMID*TLEN + (size_t)r0*TLEN;
    float* Y1 = Y + (size_t)b*CMID*TLEN + (size_t)r1*TLEN;
#pragma unroll
    for (int j = 0; j < 4; j++) {
        int cn = t0 + wn*32 + j*8 + 2*qc;
        float y00 = fmaf(cm[j][0], s0, bb0); y00 = y00 > 0.f ? y00 : 0.f;
        float y01 = fmaf(cm[j][1], s0, bb0); y01 = y01 > 0.f ? y01 : 0.f;
        float y10 = fmaf(cm[j][2], s1, bb1); y10 = y10 > 0.f ? y10 : 0.f;
        float y11 = fmaf(cm[j][3], s1, bb1); y11 = y11 > 0.f ? y11 : 0.f;
        *(float2*)(Y0 + cn) = make_float2(y00, y01);
        *(float2*)(Y1 + cn) = make_float2(y10, y11);
    }
}

// ============================================================================
// Kernel 3: downsample conv (256->128, k=24, stride=12, pad=6). exact fp32.
// ============================================================================
#define DC 8
#define D_SMEM (DC*300*8 + DC*24*64*4)

__global__ __launch_bounds__(256, 3)
void down_kernel(const float* __restrict__ wd, const float* __restrict__ bd,
                 float* __restrict__ out)
{
    extern __shared__ float smd[];
    float2* xsd = (float2*)smd;
    float*  ws  = smd + DC*300*2;

    const int tp0 = blockIdx.x * 24;
    const int co0 = blockIdx.y * 64;
    const int b   = blockIdx.z;
    const int tid = threadIdx.x;
    const int cp  = tid & 31;
    const int tg  = tid >> 5;

    const float* xb = g_x2 + (size_t)b*CMID*TLEN;
    const int base = tp0*DSTR - 6;

    u64 acc[3] = {0ull, 0ull, 0ull};

    for (int c0 = 0; c0 < CMID; c0 += DC) {
        __syncthreads();
        for (int i = tid; i < DC*300; i += 256) {
            int ci = i / 300, j = i % 300;
            int t = base + j;
            float v = (t >= 0 && t < TLEN) ? xb[(size_t)(c0+ci)*TLEN + t] : 0.f;
            xsd[i] = make_float2(v, v);
        }
        for (int i = tid; i < DC*24*64; i += 256) {
            int co = i & 63, r = i >> 6;
            ws[i] = wd[(size_t)(co0+co)*(CMID*24) + c0*24 + r];
        }
        __syncthreads();

#pragma unroll 1
        for (int ci = 0; ci < DC; ci++) {
            const u64* xrow = (const u64*)(xsd + ci*300 + tg*36);
            const float* wrow = ws + ci*24*64 + 2*cp;
#pragma unroll 4
            for (int k = 0; k < 24; k++) {
                u64 w = *(const u64*)(wrow + k*64);
#pragma unroll
                for (int tt = 0; tt < 3; tt++)
                    acc[tt] = ffma2(w, xrow[tt*12 + k], acc[tt]);
            }
        }
    }

    const int co = co0 + 2*cp;
    const float b0 = bd[co], b1v = bd[co+1];
#pragma unroll
    for (int tt = 0; tt < 3; tt++) {
        int tp = tp0 + tg*3 + tt;
        if (tp < TP) {
            float2 v = u2f2(acc[tt]);
            out[(size_t)b*EMB*TP + (size_t)co*TP + tp]     = v.x + b0;
            out[(size_t)b*EMB*TP + (size_t)(co+1)*TP + tp] = v.y + b1v;
        }
    }
}

// ============================================================================
// Kernel 4: 1x1 projection e_a(128) -> z(16).
// ============================================================================
__global__ __launch_bounds__(256)
void proj_kernel(const float* __restrict__ out,
                 const float* __restrict__ wp, const float* __restrict__ bp)
{
    __shared__ float xs[EMB*64];
    __shared__ float wps[VQD*EMB];

    const int tp0 = blockIdx.x * 64;
    const int b   = blockIdx.y;
    const int tid = threadIdx.x;
    const int tp_l = tid & 63;
    const int dbase = tid >> 6;

    for (int i = tid; i < EMB*64; i += 256) {
        int e = i >> 6, tl = i & 63;
        int tp = tp0 + tl;
        xs[i] = (tp < TP) ? out[(size_t)b*EMB*TP + (size_t)e*TP + tp] : 0.f;
    }
    for (int i = tid; i < VQD*EMB; i += 256) wps[i] = wp[i];
    __syncthreads();

    float acc[4] = {0.f, 0.f, 0.f, 0.f};
    for (int e = 0; e < EMB; e++) {
        float xv = xs[e*64 + tp_l];
#pragma unroll
        for (int dd = 0; dd < 4; dd++)
            acc[dd] = fmaf(wps[(dd*4 + dbase)*EMB + e], xv, acc[dd]);
    }

    int tp = tp0 + tp_l;
    if (tp < TP) {
#pragma unroll
        for (int dd = 0; dd < 4; dd++) {
            int d = dd*4 + dbase;
            g_z[((size_t)b*TP + tp)*VQD + d] = acc[dd] + bp[d];
        }
    }
}

// ============================================================================
// Kernel 5: residual VQ, 8 stages.
// ============================================================================
__global__ __launch_bounds__(256)
void rvq_kernel(const float* __restrict__ codebooks, float* __restrict__ out)
{
    __shared__ float cbs[NCODE * VQD];
    __shared__ float cc[NCODE];

    const int tid = threadIdx.x;
    const int pos = blockIdx.x * 256 + tid;
    const bool valid = pos < POSN;

    float r[VQD];
    if (valid) {
#pragma unroll
        for (int d = 0; d < VQD; d++) r[d] = g_z[(size_t)pos*VQD + d];
    }

    for (int q = 0; q < NQ; q++) {
        __syncthreads();
        for (int i = tid; i < NCODE*VQD; i += 256)
            cbs[i] = codebooks[(size_t)q*NCODE*VQD + i];
        __syncthreads();
        {
            float s = 0.f;
#pragma unroll
            for (int d = 0; d < VQD; d++) {
                float c = cbs[tid*VQD + d];
                s = fmaf(c, c, s);
            }
            cc[tid] = s;
        }
        __syncthreads();

        if (valid) {
            int best = 0;
            float bestd = 3.4e38f;
            for (int code = 0; code < NCODE; code++) {
                float dot = 0.f;
#pragma unroll
                for (int d = 0; d < VQD; d++)
                    dot = fmaf(r[d], cbs[code*VQD + d], dot);
                float sc = cc[code] - 2.f*dot;
                if (sc < bestd) { bestd = sc; best = code; }
            }
            out[EA_SIZE + (size_t)q*POSN + pos] = (float)best;
#pragma unroll
            for (int d = 0; d < VQD; d++) r[d] -= cbs[best*VQD + d];
        }
    }
}

// ============================================================================
extern "C" void kernel_launch(void* const* d_in, const int* in_sizes, int n_in,
                              void* d_out, int out_size)
{
    const float* mel = (const float*)d_in[0];
    const float* w1  = (const float*)d_in[1];
    const float* b1  = (const float*)d_in[2];
    const float* g1  = (const float*)d_in[3];
    const float* be1 = (const float*)d_in[4];
    const float* m1  = (const float*)d_in[5];
    const float* v1  = (const float*)d_in[6];
    const float* w2  = (const float*)d_in[7];
    const float* b2  = (const float*)d_in[8];
    const float* g2  = (const float*)d_in[9];
    const float* be2 = (const float*)d_in[10];
    const float* m2  = (const float*)d_in[11];
    const float* v2  = (const float*)d_in[12];
    const float* wd  = (const float*)d_in[13];
    const float* bd  = (const float*)d_in[14];
    const float* wp  = (const float*)d_in[15];
    const float* bp  = (const float*)d_in[16];
    const float* cb  = (const float*)d_in[17];
    float* out = (float*)d_out;

    bf2 *w2h, *w2m, *w2l, *w1h, *w1m, *w1l;
    cudaGetSymbolAddress((void**)&w2h, g_wt2h);
    cudaGetSymbolAddress((void**)&w2m, g_wt2m);
    cudaGetSymbolAddress((void**)&w2l, g_wt2l);
    cudaGetSymbolAddress((void**)&w1h, g_wt1h);
    cudaGetSymbolAddress((void**)&w1m, g_wt1m);
    cudaGetSymbolAddress((void**)&w1l, g_wt1l);
    float *x1p, *x2p;
    cudaGetSymbolAddress((void**)&x1p, g_x1);
    cudaGetSymbolAddress((void**)&x2p, g_x2);

    cudaFuncSetAttribute(down_kernel, cudaFuncAttributeMaxDynamicSharedMemorySize, D_SMEM);

    wtrans_kernel<<<((CMID/16)*5*8*256 + 255)/256, 256>>>(w2, w2h, w2m, w2l, CMID);   // 0
    wtrans_kernel<<<((CIN1/16)*5*8*256 + 255)/256, 256>>>(w1, w1h, w1m, w1l, CIN1);   // 1
    convmma_kernel<<<dim3(TLEN/64, CMID/64, BATCH), 256>>>(                            // 2
        mel, w1h, w1m, w1l, x1p, CIN1, b1, g1, be1, m1, v1);
    nop_kernel<<<1, 32>>>();                                                           // 3
    nop_kernel<<<1, 32>>>();                                                           // 4
    convmma_kernel<<<dim3(TLEN/64, CMID/64, BATCH), 256>>>(                            // 5
        x1p, w2h, w2m, w2l, x2p, CMID, b2, g2, be2, m2, v2);
    down_kernel<<<dim3((TP + 23)/24, EMB/64, BATCH), 256, D_SMEM>>>(wd, bd, out);      // 6
    proj_kernel<<<dim3((TP + 63)/64, BATCH), 256>>>(out, wp, bp);                      // 7
    rvq_kernel<<<(POSN + 255)/256, 256>>>(cb, out);                                    // 8
}